// round 1
// baseline (speedup 1.0000x reference)
#include <cuda_runtime.h>
#include <math_constants.h>

#define S_LEN 8192
#define D_IN  512
#define D_OUT 64

// Scratch for projected Q/K/V (device globals: no allocation in kernel_launch)
__device__ float g_Q[S_LEN * D_OUT];
__device__ float g_K[S_LEN * D_OUT];
__device__ float g_V[S_LEN * D_OUT];

// ---------------------------------------------------------------------------
// Kernel 1: QKV projection.  C = X @ W^T,  X[S,512], W[64,512], C[S,64].
// grid = (S/64, 3), 256 threads. Each thread computes a 4x4 micro-tile.
// Smem staged k-slices stored k-major so inner reads are LDS.128 conflict-free.
// ---------------------------------------------------------------------------
__global__ __launch_bounds__(256) void qkv_proj_kernel(
    const float* __restrict__ x,
    const float* __restrict__ Wq,
    const float* __restrict__ Wk,
    const float* __restrict__ Wv)
{
    __shared__ float Xs[16][64];   // [kk][row]
    __shared__ float Ws[16][64];   // [kk][col]

    const float* W;
    float* C;
    if (blockIdx.y == 0)      { W = Wq; C = g_Q; }
    else if (blockIdx.y == 1) { W = Wk; C = g_K; }
    else                      { W = Wv; C = g_V; }

    const int rbase = blockIdx.x * 64;
    const int tid = threadIdx.x;
    const int tx = tid & 15;          // col group
    const int ty = tid >> 4;          // row group
    const int lrow = tid & 63;        // 0..63  (row for X load / col for W load)
    const int lk   = (tid >> 6) << 2; // {0,4,8,12}

    float acc[4][4] = {};

    for (int k0 = 0; k0 < D_IN; k0 += 16) {
        float4 xv = *(const float4*)&x[(rbase + lrow) * D_IN + k0 + lk];
        float4 wv = *(const float4*)&W[lrow * D_IN + k0 + lk];
        Xs[lk + 0][lrow] = xv.x; Xs[lk + 1][lrow] = xv.y;
        Xs[lk + 2][lrow] = xv.z; Xs[lk + 3][lrow] = xv.w;
        Ws[lk + 0][lrow] = wv.x; Ws[lk + 1][lrow] = wv.y;
        Ws[lk + 2][lrow] = wv.z; Ws[lk + 3][lrow] = wv.w;
        __syncthreads();

        #pragma unroll
        for (int kk = 0; kk < 16; kk++) {
            float4 a = *(const float4*)&Xs[kk][ty * 4];
            float4 b = *(const float4*)&Ws[kk][tx * 4];
            acc[0][0] += a.x * b.x; acc[0][1] += a.x * b.y;
            acc[0][2] += a.x * b.z; acc[0][3] += a.x * b.w;
            acc[1][0] += a.y * b.x; acc[1][1] += a.y * b.y;
            acc[1][2] += a.y * b.z; acc[1][3] += a.y * b.w;
            acc[2][0] += a.z * b.x; acc[2][1] += a.z * b.y;
            acc[2][2] += a.z * b.z; acc[2][3] += a.z * b.w;
            acc[3][0] += a.w * b.x; acc[3][1] += a.w * b.y;
            acc[3][2] += a.w * b.z; acc[3][3] += a.w * b.w;
        }
        __syncthreads();
    }

    #pragma unroll
    for (int i = 0; i < 4; i++) {
        *(float4*)&C[(rbase + ty * 4 + i) * D_OUT + tx * 4] =
            make_float4(acc[i][0], acc[i][1], acc[i][2], acc[i][3]);
    }
}

// ---------------------------------------------------------------------------
// Kernel 2: causal flash attention, fp32.
// BLOCK_M = BLOCK_N = 64, D = 64, 256 threads, 4x4 micro-tile per thread.
// Q/K staged d-major in smem; V row-major; P roundtrips through smem for PV.
// Online softmax: per-row max/sum via shfl reductions over 16-lane segments.
// Dynamic smem = 4 * 64*64*4 = 64 KB.
// ---------------------------------------------------------------------------
__global__ __launch_bounds__(256) void attn_kernel(float* __restrict__ out)
{
    extern __shared__ float sm[];
    float* Qs = sm;                 // [d][r]  64x64
    float* Ks = sm + 64 * 64;       // [d][k]
    float* Vs = sm + 2 * 64 * 64;   // [k][c]
    float* Ps = sm + 3 * 64 * 64;   // [r][k]

    const int mblk = blockIdx.x;
    const int qbase = mblk * 64;
    const int tid = threadIdx.x;
    const int tx = tid & 15;
    const int ty = tid >> 4;
    const int lrow = tid & 63;
    const int ld0  = (tid >> 6) << 2;

    // Load Q tile transposed (d-major)
    #pragma unroll
    for (int d0 = 0; d0 < 64; d0 += 16) {
        float4 v = *(const float4*)&g_Q[(qbase + lrow) * D_OUT + d0 + ld0];
        Qs[(d0 + ld0 + 0) * 64 + lrow] = v.x;
        Qs[(d0 + ld0 + 1) * 64 + lrow] = v.y;
        Qs[(d0 + ld0 + 2) * 64 + lrow] = v.z;
        Qs[(d0 + ld0 + 3) * 64 + lrow] = v.w;
    }

    float Ob[4][4] = {};
    float mrow[4] = {-CUDART_INF_F, -CUDART_INF_F, -CUDART_INF_F, -CUDART_INF_F};
    float lsum[4] = {0.f, 0.f, 0.f, 0.f};

    const float SC = 0.125f * 1.4426950408889634f;  // (1/sqrt(64)) * log2(e)

    for (int nblk = 0; nblk <= mblk; nblk++) {
        const int kbase = nblk * 64;
        __syncthreads();   // previous PV done before overwriting K/V

        // K tile transposed (d-major)
        #pragma unroll
        for (int d0 = 0; d0 < 64; d0 += 16) {
            float4 v = *(const float4*)&g_K[(kbase + lrow) * D_OUT + d0 + ld0];
            Ks[(d0 + ld0 + 0) * 64 + lrow] = v.x;
            Ks[(d0 + ld0 + 1) * 64 + lrow] = v.y;
            Ks[(d0 + ld0 + 2) * 64 + lrow] = v.z;
            Ks[(d0 + ld0 + 3) * 64 + lrow] = v.w;
        }
        // V tile row-major
        {
            const int c4 = tx * 4;
            #pragma unroll
            for (int k = ty; k < 64; k += 16) {
                *(float4*)&Vs[k * 64 + c4] =
                    *(const float4*)&g_V[(kbase + k) * D_OUT + c4];
            }
        }
        __syncthreads();

        // Scores: 4x4 per thread, dot over d=64
        float s[4][4] = {};
        #pragma unroll
        for (int d = 0; d < 64; d++) {
            float4 a = *(const float4*)&Qs[d * 64 + ty * 4];
            float4 b = *(const float4*)&Ks[d * 64 + tx * 4];
            s[0][0] += a.x * b.x; s[0][1] += a.x * b.y;
            s[0][2] += a.x * b.z; s[0][3] += a.x * b.w;
            s[1][0] += a.y * b.x; s[1][1] += a.y * b.y;
            s[1][2] += a.y * b.z; s[1][3] += a.y * b.w;
            s[2][0] += a.z * b.x; s[2][1] += a.z * b.y;
            s[2][2] += a.z * b.z; s[2][3] += a.z * b.w;
            s[3][0] += a.w * b.x; s[3][1] += a.w * b.y;
            s[3][2] += a.w * b.z; s[3][3] += a.w * b.w;
        }

        if (nblk == mblk) {   // diagonal tile: mask key > query
            #pragma unroll
            for (int i = 0; i < 4; i++)
                #pragma unroll
                for (int j = 0; j < 4; j++)
                    if (tx * 4 + j > ty * 4 + i) s[i][j] = -CUDART_INF_F;
        }

        // Online softmax per row
        #pragma unroll
        for (int i = 0; i < 4; i++) {
            float rm = fmaxf(fmaxf(s[i][0], s[i][1]), fmaxf(s[i][2], s[i][3]));
            #pragma unroll
            for (int off = 1; off < 16; off <<= 1)
                rm = fmaxf(rm, __shfl_xor_sync(0xffffffffu, rm, off, 16));
            float mn = fmaxf(mrow[i], rm);
            float alpha = exp2f((mrow[i] - mn) * SC);
            mrow[i] = mn;
            float p0 = exp2f((s[i][0] - mn) * SC);
            float p1 = exp2f((s[i][1] - mn) * SC);
            float p2 = exp2f((s[i][2] - mn) * SC);
            float p3 = exp2f((s[i][3] - mn) * SC);
            float rs = (p0 + p1) + (p2 + p3);
            #pragma unroll
            for (int off = 1; off < 16; off <<= 1)
                rs += __shfl_xor_sync(0xffffffffu, rs, off, 16);
            lsum[i] = lsum[i] * alpha + rs;
            Ob[i][0] *= alpha; Ob[i][1] *= alpha;
            Ob[i][2] *= alpha; Ob[i][3] *= alpha;
            *(float4*)&Ps[(ty * 4 + i) * 64 + tx * 4] = make_float4(p0, p1, p2, p3);
        }
        __syncthreads();

        // O += P @ V   (4 rows x 4 cols per thread, k in chunks of 4)
        #pragma unroll
        for (int k0 = 0; k0 < 64; k0 += 4) {
            float vbk[4][4];
            #pragma unroll
            for (int kk = 0; kk < 4; kk++) {
                float4 t = *(const float4*)&Vs[(k0 + kk) * 64 + tx * 4];
                vbk[kk][0] = t.x; vbk[kk][1] = t.y; vbk[kk][2] = t.z; vbk[kk][3] = t.w;
            }
            #pragma unroll
            for (int i = 0; i < 4; i++) {
                float4 pt = *(const float4*)&Ps[(ty * 4 + i) * 64 + k0];
                float pr[4] = {pt.x, pt.y, pt.z, pt.w};
                #pragma unroll
                for (int kk = 0; kk < 4; kk++) {
                    Ob[i][0] += pr[kk] * vbk[kk][0];
                    Ob[i][1] += pr[kk] * vbk[kk][1];
                    Ob[i][2] += pr[kk] * vbk[kk][2];
                    Ob[i][3] += pr[kk] * vbk[kk][3];
                }
            }
        }
    }

    // Normalize + write
    #pragma unroll
    for (int i = 0; i < 4; i++) {
        float inv = 1.0f / lsum[i];
        *(float4*)&out[(qbase + ty * 4 + i) * D_OUT + tx * 4] =
            make_float4(Ob[i][0] * inv, Ob[i][1] * inv, Ob[i][2] * inv, Ob[i][3] * inv);
    }
}

// ---------------------------------------------------------------------------
extern "C" void kernel_launch(void* const* d_in, const int* in_sizes, int n_in,
                              void* d_out, int out_size)
{
    const float* x  = (const float*)d_in[0];
    const float* Wq = (const float*)d_in[1];
    const float* Wk = (const float*)d_in[2];
    const float* Wv = (const float*)d_in[3];
    float* out = (float*)d_out;

    // 64 KB dynamic smem for the attention kernel (> 48 KB default).
    // Idempotent; not a stream op, safe under graph capture.
    cudaFuncSetAttribute(attn_kernel,
                         cudaFuncAttributeMaxDynamicSharedMemorySize, 65536);

    dim3 g1(S_LEN / 64, 3);
    qkv_proj_kernel<<<g1, 256>>>(x, Wq, Wk, Wv);
    attn_kernel<<<S_LEN / 64, 256, 65536>>>(out);
}

// round 2
// speedup vs baseline: 2.1389x; 2.1389x over previous
#include <cuda_runtime.h>
#include <math_constants.h>
#include <cstdint>

#define S_LEN 8192
#define D_IN  512
#define D_OUT 64

// Scratch for projected Q/K/V (device globals: no allocation in kernel_launch)
__device__ float g_Q[S_LEN * D_OUT];
__device__ float g_K[S_LEN * D_OUT];
__device__ float g_V[S_LEN * D_OUT];

// ---------------------------------------------------------------------------
// Kernel 1: QKV projection (exact fp32).  C = X @ W^T,  X[S,512], W[64,512].
// grid = (S/64, 3), 256 threads, 4x4 micro-tile per thread. (unchanged R1)
// ---------------------------------------------------------------------------
__global__ __launch_bounds__(256) void qkv_proj_kernel(
    const float* __restrict__ x,
    const float* __restrict__ Wq,
    const float* __restrict__ Wk,
    const float* __restrict__ Wv)
{
    __shared__ float Xs[16][64];
    __shared__ float Ws[16][64];

    const float* W;
    float* C;
    if (blockIdx.y == 0)      { W = Wq; C = g_Q; }
    else if (blockIdx.y == 1) { W = Wk; C = g_K; }
    else                      { W = Wv; C = g_V; }

    const int rbase = blockIdx.x * 64;
    const int tid = threadIdx.x;
    const int tx = tid & 15;
    const int ty = tid >> 4;
    const int lrow = tid & 63;
    const int lk   = (tid >> 6) << 2;

    float acc[4][4] = {};

    for (int k0 = 0; k0 < D_IN; k0 += 16) {
        float4 xv = *(const float4*)&x[(rbase + lrow) * D_IN + k0 + lk];
        float4 wv = *(const float4*)&W[lrow * D_IN + k0 + lk];
        Xs[lk + 0][lrow] = xv.x; Xs[lk + 1][lrow] = xv.y;
        Xs[lk + 2][lrow] = xv.z; Xs[lk + 3][lrow] = xv.w;
        Ws[lk + 0][lrow] = wv.x; Ws[lk + 1][lrow] = wv.y;
        Ws[lk + 2][lrow] = wv.z; Ws[lk + 3][lrow] = wv.w;
        __syncthreads();

        #pragma unroll
        for (int kk = 0; kk < 16; kk++) {
            float4 a = *(const float4*)&Xs[kk][ty * 4];
            float4 b = *(const float4*)&Ws[kk][tx * 4];
            acc[0][0] += a.x * b.x; acc[0][1] += a.x * b.y;
            acc[0][2] += a.x * b.z; acc[0][3] += a.x * b.w;
            acc[1][0] += a.y * b.x; acc[1][1] += a.y * b.y;
            acc[1][2] += a.y * b.z; acc[1][3] += a.y * b.w;
            acc[2][0] += a.z * b.x; acc[2][1] += a.z * b.y;
            acc[2][2] += a.z * b.z; acc[2][3] += a.z * b.w;
            acc[3][0] += a.w * b.x; acc[3][1] += a.w * b.y;
            acc[3][2] += a.w * b.z; acc[3][3] += a.w * b.w;
        }
        __syncthreads();
    }

    #pragma unroll
    for (int i = 0; i < 4; i++) {
        *(float4*)&C[(rbase + ty * 4 + i) * D_OUT + tx * 4] =
            make_float4(acc[i][0], acc[i][1], acc[i][2], acc[i][3]);
    }
}

// ---------------------------------------------------------------------------
// tf32 mma.sync helpers
// ---------------------------------------------------------------------------
__device__ __forceinline__ uint32_t f2tf32(float x) {
    uint32_t r;
    asm("cvt.rna.tf32.f32 %0, %1;" : "=r"(r) : "f"(x));
    return r;
}

__device__ __forceinline__ float fast_ex2(float x) {
    float y;
    asm("ex2.approx.ftz.f32 %0, %1;" : "=f"(y) : "f"(x));
    return y;
}

__device__ __forceinline__ void mma_tf32(
    float& d0, float& d1, float& d2, float& d3,
    uint32_t a0, uint32_t a1, uint32_t a2, uint32_t a3,
    uint32_t b0, uint32_t b1)
{
    asm volatile(
        "mma.sync.aligned.m16n8k8.row.col.f32.tf32.tf32.f32 "
        "{%0,%1,%2,%3}, {%4,%5,%6,%7}, {%8,%9}, {%0,%1,%2,%3};\n"
        : "+f"(d0), "+f"(d1), "+f"(d2), "+f"(d3)
        : "r"(a0), "r"(a1), "r"(a2), "r"(a3), "r"(b0), "r"(b1));
}

// ---------------------------------------------------------------------------
// Kernel 2: causal flash attention with tf32 tensor cores.
// BLOCK_M = BLOCK_N = 64, D = 64. 128 threads = 4 warps; warp w owns rows
// [w*16, w*16+16) of the Q block and the full n=64 / d=64 extent.
// smem: Ks/Vs staged [key][d] (stride 68, conflict-free for both the
// B-fragment pattern of QK and of PV), Ps per-warp P roundtrip (C-layout ->
// A-layout, warp-local, __syncwarp only).
// Online softmax per 16 rows, quad shfl reductions. fp32 accumulators.
// ---------------------------------------------------------------------------
#define SMS 68   // smem row stride (floats)

__global__ __launch_bounds__(128) void attn_tc_kernel(float* __restrict__ out)
{
    extern __shared__ uint32_t sm_u[];
    uint32_t* Ks = sm_u;                // [64][SMS] tf32 bits
    uint32_t* Vs = sm_u + 64 * SMS;     // [64][SMS]
    uint32_t* Ps = sm_u + 2 * 64 * SMS; // [64][SMS]

    const int mblk  = blockIdx.x;
    const int qbase = mblk * 64;
    const int tid   = threadIdx.x;
    const int wid   = tid >> 5;
    const int lane  = tid & 31;
    const int g     = lane >> 2;   // group id (row within 8-row half)
    const int qd    = lane & 3;    // quad lane
    const int mr    = wid * 16;    // warp row base within block

    const float SC = 0.125f * 1.4426950408889634f; // (1/sqrt(64))*log2(e)

    // Q fragments, register-resident for all tiles: qa[kt][0..3]
    uint32_t qa[8][4];
    #pragma unroll
    for (int kt = 0; kt < 8; kt++) {
        const float* q0 = &g_Q[(qbase + mr + g) * D_OUT + kt * 8 + qd];
        const float* q1 = &g_Q[(qbase + mr + g + 8) * D_OUT + kt * 8 + qd];
        qa[kt][0] = f2tf32(q0[0]);
        qa[kt][1] = f2tf32(q1[0]);
        qa[kt][2] = f2tf32(q0[4]);
        qa[kt][3] = f2tf32(q1[4]);
    }

    float O[8][4] = {};
    float m0 = -CUDART_INF_F, m1 = -CUDART_INF_F;
    float l0 = 0.f, l1 = 0.f;

    for (int nblk = 0; nblk <= mblk; nblk++) {
        const int kbase = nblk * 64;
        __syncthreads();  // previous tile's smem reads done

        // Stage K and V tiles [key][d] as tf32 bits. 1024 float4s / 128 thr.
        for (int i = tid; i < 64 * 16; i += 128) {
            int row = i >> 4;
            int c4  = (i & 15) << 2;
            float4 kv = *(const float4*)&g_K[(kbase + row) * D_OUT + c4];
            float4 vv = *(const float4*)&g_V[(kbase + row) * D_OUT + c4];
            uint32_t* kd = &Ks[row * SMS + c4];
            uint32_t* vd = &Vs[row * SMS + c4];
            kd[0] = f2tf32(kv.x); kd[1] = f2tf32(kv.y);
            kd[2] = f2tf32(kv.z); kd[3] = f2tf32(kv.w);
            vd[0] = f2tf32(vv.x); vd[1] = f2tf32(vv.y);
            vd[2] = f2tf32(vv.z); vd[3] = f2tf32(vv.w);
        }
        __syncthreads();

        // ----- scores S = Q K^T : warp computes m16 x n64 -----
        float s[8][4] = {};
        #pragma unroll
        for (int nt = 0; nt < 8; nt++) {
            #pragma unroll
            for (int kt = 0; kt < 8; kt++) {
                uint32_t b0 = Ks[(nt * 8 + g) * SMS + kt * 8 + qd];
                uint32_t b1 = Ks[(nt * 8 + g) * SMS + kt * 8 + qd + 4];
                mma_tf32(s[nt][0], s[nt][1], s[nt][2], s[nt][3],
                         qa[kt][0], qa[kt][1], qa[kt][2], qa[kt][3], b0, b1);
            }
        }

        // causal mask on diagonal tile (kbase == qbase -> local compare)
        if (nblk == mblk) {
            const int r0 = mr + g, r1 = mr + g + 8;
            #pragma unroll
            for (int nt = 0; nt < 8; nt++) {
                int c = nt * 8 + 2 * qd;
                if (c     > r0) s[nt][0] = -CUDART_INF_F;
                if (c + 1 > r0) s[nt][1] = -CUDART_INF_F;
                if (c     > r1) s[nt][2] = -CUDART_INF_F;
                if (c + 1 > r1) s[nt][3] = -CUDART_INF_F;
            }
        }

        // ----- online softmax (rows r0 = mr+g, r1 = mr+g+8) -----
        float rm0 = -CUDART_INF_F, rm1 = -CUDART_INF_F;
        #pragma unroll
        for (int nt = 0; nt < 8; nt++) {
            rm0 = fmaxf(rm0, fmaxf(s[nt][0], s[nt][1]));
            rm1 = fmaxf(rm1, fmaxf(s[nt][2], s[nt][3]));
        }
        rm0 = fmaxf(rm0, __shfl_xor_sync(0xffffffffu, rm0, 1));
        rm0 = fmaxf(rm0, __shfl_xor_sync(0xffffffffu, rm0, 2));
        rm1 = fmaxf(rm1, __shfl_xor_sync(0xffffffffu, rm1, 1));
        rm1 = fmaxf(rm1, __shfl_xor_sync(0xffffffffu, rm1, 2));

        float mn0 = fmaxf(m0, rm0);
        float mn1 = fmaxf(m1, rm1);
        float al0 = fast_ex2((m0 - mn0) * SC);
        float al1 = fast_ex2((m1 - mn1) * SC);
        m0 = mn0; m1 = mn1;

        float rs0 = 0.f, rs1 = 0.f;
        #pragma unroll
        for (int nt = 0; nt < 8; nt++) {
            float p00 = fast_ex2((s[nt][0] - mn0) * SC);
            float p01 = fast_ex2((s[nt][1] - mn0) * SC);
            float p10 = fast_ex2((s[nt][2] - mn1) * SC);
            float p11 = fast_ex2((s[nt][3] - mn1) * SC);
            rs0 += p00 + p01;
            rs1 += p10 + p11;
            // store P (tf32 bits) into warp-local region, C-layout positions
            uint32_t* p0 = &Ps[(mr + g) * SMS + nt * 8 + 2 * qd];
            uint32_t* p1 = &Ps[(mr + g + 8) * SMS + nt * 8 + 2 * qd];
            *(uint2*)p0 = make_uint2(f2tf32(p00), f2tf32(p01));
            *(uint2*)p1 = make_uint2(f2tf32(p10), f2tf32(p11));
        }
        rs0 += __shfl_xor_sync(0xffffffffu, rs0, 1);
        rs0 += __shfl_xor_sync(0xffffffffu, rs0, 2);
        rs1 += __shfl_xor_sync(0xffffffffu, rs1, 1);
        rs1 += __shfl_xor_sync(0xffffffffu, rs1, 2);
        l0 = l0 * al0 + rs0;
        l1 = l1 * al1 + rs1;

        // rescale accumulators
        #pragma unroll
        for (int nt = 0; nt < 8; nt++) {
            O[nt][0] *= al0; O[nt][1] *= al0;
            O[nt][2] *= al1; O[nt][3] *= al1;
        }
        __syncwarp();

        // ----- O += P V : A = P (m16 x k64), B = V [key][d] -----
        #pragma unroll
        for (int kt = 0; kt < 8; kt++) {
            uint32_t pa0 = Ps[(mr + g) * SMS + kt * 8 + qd];
            uint32_t pa1 = Ps[(mr + g + 8) * SMS + kt * 8 + qd];
            uint32_t pa2 = Ps[(mr + g) * SMS + kt * 8 + qd + 4];
            uint32_t pa3 = Ps[(mr + g + 8) * SMS + kt * 8 + qd + 4];
            #pragma unroll
            for (int nt = 0; nt < 8; nt++) {
                uint32_t b0 = Vs[(kt * 8 + qd) * SMS + nt * 8 + g];
                uint32_t b1 = Vs[(kt * 8 + qd + 4) * SMS + nt * 8 + g];
                mma_tf32(O[nt][0], O[nt][1], O[nt][2], O[nt][3],
                         pa0, pa1, pa2, pa3, b0, b1);
            }
        }
    }

    // ----- normalize + write -----
    float inv0 = 1.0f / l0;
    float inv1 = 1.0f / l1;
    #pragma unroll
    for (int nt = 0; nt < 8; nt++) {
        float* o0 = &out[(qbase + mr + g) * D_OUT + nt * 8 + 2 * qd];
        float* o1 = &out[(qbase + mr + g + 8) * D_OUT + nt * 8 + 2 * qd];
        *(float2*)o0 = make_float2(O[nt][0] * inv0, O[nt][1] * inv0);
        *(float2*)o1 = make_float2(O[nt][2] * inv1, O[nt][3] * inv1);
    }
}

// ---------------------------------------------------------------------------
extern "C" void kernel_launch(void* const* d_in, const int* in_sizes, int n_in,
                              void* d_out, int out_size)
{
    const float* x  = (const float*)d_in[0];
    const float* Wq = (const float*)d_in[1];
    const float* Wk = (const float*)d_in[2];
    const float* Wv = (const float*)d_in[3];
    float* out = (float*)d_out;

    const int attn_smem = 3 * 64 * SMS * 4;  // 52224 bytes
    cudaFuncSetAttribute(attn_tc_kernel,
                         cudaFuncAttributeMaxDynamicSharedMemorySize, attn_smem);

    dim3 g1(S_LEN / 64, 3);
    qkv_proj_kernel<<<g1, 256>>>(x, Wq, Wk, Wv);
    attn_tc_kernel<<<S_LEN / 64, 128, attn_smem>>>(out);
}

// round 3
// speedup vs baseline: 3.9251x; 1.8351x over previous
#include <cuda_runtime.h>
#include <math_constants.h>
#include <cstdint>

#define S_LEN 8192
#define D_IN  512
#define D_OUT 64

#define CHUNK_TILES 16          // key tiles (of 64) per chunk CTA
#define MAX_CHUNKS  8           // ceil(128 / 16)

// Scratch (device globals: no allocation in kernel_launch)
__device__ float g_Q[S_LEN * D_OUT];
__device__ float g_K[S_LEN * D_OUT];
__device__ float g_V[S_LEN * D_OUT];
// split-K partials: per (qblk, chunk): unnormalized O[64][64], m[64], l[64]
__device__ float g_Op[128 * MAX_CHUNKS * 64 * 64];
__device__ float g_m [128 * MAX_CHUNKS * 64];
__device__ float g_l [128 * MAX_CHUNKS * 64];

// ---------------------------------------------------------------------------
// Kernel 1: QKV projection (exact fp32).  C = X @ W^T. (unchanged from R1)
// ---------------------------------------------------------------------------
__global__ __launch_bounds__(256) void qkv_proj_kernel(
    const float* __restrict__ x,
    const float* __restrict__ Wq,
    const float* __restrict__ Wk,
    const float* __restrict__ Wv)
{
    __shared__ float Xs[16][64];
    __shared__ float Ws[16][64];

    const float* W;
    float* C;
    if (blockIdx.y == 0)      { W = Wq; C = g_Q; }
    else if (blockIdx.y == 1) { W = Wk; C = g_K; }
    else                      { W = Wv; C = g_V; }

    const int rbase = blockIdx.x * 64;
    const int tid = threadIdx.x;
    const int tx = tid & 15;
    const int ty = tid >> 4;
    const int lrow = tid & 63;
    const int lk   = (tid >> 6) << 2;

    float acc[4][4] = {};

    for (int k0 = 0; k0 < D_IN; k0 += 16) {
        float4 xv = *(const float4*)&x[(rbase + lrow) * D_IN + k0 + lk];
        float4 wv = *(const float4*)&W[lrow * D_IN + k0 + lk];
        Xs[lk + 0][lrow] = xv.x; Xs[lk + 1][lrow] = xv.y;
        Xs[lk + 2][lrow] = xv.z; Xs[lk + 3][lrow] = xv.w;
        Ws[lk + 0][lrow] = wv.x; Ws[lk + 1][lrow] = wv.y;
        Ws[lk + 2][lrow] = wv.z; Ws[lk + 3][lrow] = wv.w;
        __syncthreads();

        #pragma unroll
        for (int kk = 0; kk < 16; kk++) {
            float4 a = *(const float4*)&Xs[kk][ty * 4];
            float4 b = *(const float4*)&Ws[kk][tx * 4];
            acc[0][0] += a.x * b.x; acc[0][1] += a.x * b.y;
            acc[0][2] += a.x * b.z; acc[0][3] += a.x * b.w;
            acc[1][0] += a.y * b.x; acc[1][1] += a.y * b.y;
            acc[1][2] += a.y * b.z; acc[1][3] += a.y * b.w;
            acc[2][0] += a.z * b.x; acc[2][1] += a.z * b.y;
            acc[2][2] += a.z * b.z; acc[2][3] += a.z * b.w;
            acc[3][0] += a.w * b.x; acc[3][1] += a.w * b.y;
            acc[3][2] += a.w * b.z; acc[3][3] += a.w * b.w;
        }
        __syncthreads();
    }

    #pragma unroll
    for (int i = 0; i < 4; i++) {
        *(float4*)&C[(rbase + ty * 4 + i) * D_OUT + tx * 4] =
            make_float4(acc[i][0], acc[i][1], acc[i][2], acc[i][3]);
    }
}

// ---------------------------------------------------------------------------
// tf32 mma.sync helpers
// ---------------------------------------------------------------------------
__device__ __forceinline__ uint32_t f2tf32(float x) {
    uint32_t r;
    asm("cvt.rna.tf32.f32 %0, %1;" : "=r"(r) : "f"(x));
    return r;
}

__device__ __forceinline__ float fast_ex2(float x) {
    float y;
    asm("ex2.approx.ftz.f32 %0, %1;" : "=f"(y) : "f"(x));
    return y;
}

__device__ __forceinline__ void mma_tf32(
    float& d0, float& d1, float& d2, float& d3,
    uint32_t a0, uint32_t a1, uint32_t a2, uint32_t a3,
    uint32_t b0, uint32_t b1)
{
    asm volatile(
        "mma.sync.aligned.m16n8k8.row.col.f32.tf32.tf32.f32 "
        "{%0,%1,%2,%3}, {%4,%5,%6,%7}, {%8,%9}, {%0,%1,%2,%3};\n"
        : "+f"(d0), "+f"(d1), "+f"(d2), "+f"(d3)
        : "r"(a0), "r"(a1), "r"(a2), "r"(a3), "r"(b0), "r"(b1));
}

// ---------------------------------------------------------------------------
// Kernel 2: split-K causal flash attention chunk (tf32 tensor cores).
// blockIdx.y = qblock (0..127), blockIdx.x = chunk (0..7); a chunk covers
// key tiles [16c, min(16c+15, mblk)].  Per-CTA tile math identical to R2.
// Emits unnormalized O + per-row (m, l) partials.
// ---------------------------------------------------------------------------
#define SMS 68   // smem row stride (floats)

__global__ __launch_bounds__(128) void attn_chunk_kernel()
{
    const int mblk  = blockIdx.y;
    const int chunk = blockIdx.x;
    const int n0 = chunk * CHUNK_TILES;
    if (n0 > mblk) return;                       // chunk beyond causal range
    const int n1 = min(n0 + CHUNK_TILES - 1, mblk);

    extern __shared__ uint32_t sm_u[];
    uint32_t* Ks = sm_u;                // [64][SMS] tf32 bits
    uint32_t* Vs = sm_u + 64 * SMS;     // [64][SMS]
    uint32_t* Ps = sm_u + 2 * 64 * SMS; // [64][SMS]

    const int qbase = mblk * 64;
    const int tid   = threadIdx.x;
    const int wid   = tid >> 5;
    const int lane  = tid & 31;
    const int g     = lane >> 2;
    const int qd    = lane & 3;
    const int mr    = wid * 16;

    const float SC = 0.125f * 1.4426950408889634f; // (1/sqrt(64))*log2(e)

    // Q fragments, register-resident: qa[kt][0..3]
    uint32_t qa[8][4];
    #pragma unroll
    for (int kt = 0; kt < 8; kt++) {
        const float* q0 = &g_Q[(qbase + mr + g) * D_OUT + kt * 8 + qd];
        const float* q1 = &g_Q[(qbase + mr + g + 8) * D_OUT + kt * 8 + qd];
        qa[kt][0] = f2tf32(q0[0]);
        qa[kt][1] = f2tf32(q1[0]);
        qa[kt][2] = f2tf32(q0[4]);
        qa[kt][3] = f2tf32(q1[4]);
    }

    float O[8][4] = {};
    float m0 = -CUDART_INF_F, m1 = -CUDART_INF_F;
    float l0 = 0.f, l1 = 0.f;

    for (int nblk = n0; nblk <= n1; nblk++) {
        const int kbase = nblk * 64;
        __syncthreads();

        // Stage K and V tiles [key][d] as tf32 bits
        for (int i = tid; i < 64 * 16; i += 128) {
            int row = i >> 4;
            int c4  = (i & 15) << 2;
            float4 kv = *(const float4*)&g_K[(kbase + row) * D_OUT + c4];
            float4 vv = *(const float4*)&g_V[(kbase + row) * D_OUT + c4];
            uint32_t* kd = &Ks[row * SMS + c4];
            uint32_t* vd = &Vs[row * SMS + c4];
            kd[0] = f2tf32(kv.x); kd[1] = f2tf32(kv.y);
            kd[2] = f2tf32(kv.z); kd[3] = f2tf32(kv.w);
            vd[0] = f2tf32(vv.x); vd[1] = f2tf32(vv.y);
            vd[2] = f2tf32(vv.z); vd[3] = f2tf32(vv.w);
        }
        __syncthreads();

        // ----- scores S = Q K^T -----
        float s[8][4] = {};
        #pragma unroll
        for (int nt = 0; nt < 8; nt++) {
            #pragma unroll
            for (int kt = 0; kt < 8; kt++) {
                uint32_t b0 = Ks[(nt * 8 + g) * SMS + kt * 8 + qd];
                uint32_t b1 = Ks[(nt * 8 + g) * SMS + kt * 8 + qd + 4];
                mma_tf32(s[nt][0], s[nt][1], s[nt][2], s[nt][3],
                         qa[kt][0], qa[kt][1], qa[kt][2], qa[kt][3], b0, b1);
            }
        }

        // causal mask on diagonal tile
        if (nblk == mblk) {
            const int r0 = mr + g, r1 = mr + g + 8;
            #pragma unroll
            for (int nt = 0; nt < 8; nt++) {
                int c = nt * 8 + 2 * qd;
                if (c     > r0) s[nt][0] = -CUDART_INF_F;
                if (c + 1 > r0) s[nt][1] = -CUDART_INF_F;
                if (c     > r1) s[nt][2] = -CUDART_INF_F;
                if (c + 1 > r1) s[nt][3] = -CUDART_INF_F;
            }
        }

        // ----- online softmax -----
        float rm0 = -CUDART_INF_F, rm1 = -CUDART_INF_F;
        #pragma unroll
        for (int nt = 0; nt < 8; nt++) {
            rm0 = fmaxf(rm0, fmaxf(s[nt][0], s[nt][1]));
            rm1 = fmaxf(rm1, fmaxf(s[nt][2], s[nt][3]));
        }
        rm0 = fmaxf(rm0, __shfl_xor_sync(0xffffffffu, rm0, 1));
        rm0 = fmaxf(rm0, __shfl_xor_sync(0xffffffffu, rm0, 2));
        rm1 = fmaxf(rm1, __shfl_xor_sync(0xffffffffu, rm1, 1));
        rm1 = fmaxf(rm1, __shfl_xor_sync(0xffffffffu, rm1, 2));

        float mn0 = fmaxf(m0, rm0);
        float mn1 = fmaxf(m1, rm1);
        float al0 = fast_ex2((m0 - mn0) * SC);
        float al1 = fast_ex2((m1 - mn1) * SC);
        m0 = mn0; m1 = mn1;

        float rs0 = 0.f, rs1 = 0.f;
        #pragma unroll
        for (int nt = 0; nt < 8; nt++) {
            float p00 = fast_ex2((s[nt][0] - mn0) * SC);
            float p01 = fast_ex2((s[nt][1] - mn0) * SC);
            float p10 = fast_ex2((s[nt][2] - mn1) * SC);
            float p11 = fast_ex2((s[nt][3] - mn1) * SC);
            rs0 += p00 + p01;
            rs1 += p10 + p11;
            uint32_t* p0 = &Ps[(mr + g) * SMS + nt * 8 + 2 * qd];
            uint32_t* p1 = &Ps[(mr + g + 8) * SMS + nt * 8 + 2 * qd];
            *(uint2*)p0 = make_uint2(f2tf32(p00), f2tf32(p01));
            *(uint2*)p1 = make_uint2(f2tf32(p10), f2tf32(p11));
        }
        rs0 += __shfl_xor_sync(0xffffffffu, rs0, 1);
        rs0 += __shfl_xor_sync(0xffffffffu, rs0, 2);
        rs1 += __shfl_xor_sync(0xffffffffu, rs1, 1);
        rs1 += __shfl_xor_sync(0xffffffffu, rs1, 2);
        l0 = l0 * al0 + rs0;
        l1 = l1 * al1 + rs1;

        #pragma unroll
        for (int nt = 0; nt < 8; nt++) {
            O[nt][0] *= al0; O[nt][1] *= al0;
            O[nt][2] *= al1; O[nt][3] *= al1;
        }
        __syncwarp();

        // ----- O += P V -----
        #pragma unroll
        for (int kt = 0; kt < 8; kt++) {
            uint32_t pa0 = Ps[(mr + g) * SMS + kt * 8 + qd];
            uint32_t pa1 = Ps[(mr + g + 8) * SMS + kt * 8 + qd];
            uint32_t pa2 = Ps[(mr + g) * SMS + kt * 8 + qd + 4];
            uint32_t pa3 = Ps[(mr + g + 8) * SMS + kt * 8 + qd + 4];
            #pragma unroll
            for (int nt = 0; nt < 8; nt++) {
                uint32_t b0 = Vs[(kt * 8 + qd) * SMS + nt * 8 + g];
                uint32_t b1 = Vs[(kt * 8 + qd + 4) * SMS + nt * 8 + g];
                mma_tf32(O[nt][0], O[nt][1], O[nt][2], O[nt][3],
                         pa0, pa1, pa2, pa3, b0, b1);
            }
        }
    }

    // ----- write partials (unnormalized O, per-row m and l) -----
    const int pbase = (mblk * MAX_CHUNKS + chunk) * 64;   // row base in partials
    const int r0 = mr + g, r1 = mr + g + 8;
    #pragma unroll
    for (int nt = 0; nt < 8; nt++) {
        float* o0 = &g_Op[(pbase + r0) * 64 + nt * 8 + 2 * qd];
        float* o1 = &g_Op[(pbase + r1) * 64 + nt * 8 + 2 * qd];
        *(float2*)o0 = make_float2(O[nt][0], O[nt][1]);
        *(float2*)o1 = make_float2(O[nt][2], O[nt][3]);
    }
    if (qd == 0) {
        g_m[pbase + r0] = m0;  g_m[pbase + r1] = m1;
        g_l[pbase + r0] = l0;  g_l[pbase + r1] = l1;
    }
}

// ---------------------------------------------------------------------------
// Kernel 3: combine split-K partials.  grid = 128 qblocks, 128 threads.
// Thread t: row = t/2, cols [(t&1)*32, +32).
// ---------------------------------------------------------------------------
__global__ __launch_bounds__(128) void attn_reduce_kernel(float* __restrict__ out)
{
    const int qblk = blockIdx.x;
    const int nch  = qblk / CHUNK_TILES + 1;      // chunks for this qblock
    const int tid  = threadIdx.x;
    const int r    = tid >> 1;
    const int c0   = (tid & 1) * 32;
    const float SC = 0.125f * 1.4426950408889634f;

    const int pbase = qblk * MAX_CHUNKS * 64;

    float mv[MAX_CHUNKS];
    float M = -CUDART_INF_F;
    for (int i = 0; i < nch; i++) {
        mv[i] = g_m[pbase + i * 64 + r];
        M = fmaxf(M, mv[i]);
    }

    float acc[32];
    #pragma unroll
    for (int j = 0; j < 32; j++) acc[j] = 0.f;
    float wl = 0.f;

    for (int i = 0; i < nch; i++) {
        float w = fast_ex2((mv[i] - M) * SC);
        wl += w * g_l[pbase + i * 64 + r];
        const float* Op = &g_Op[(pbase + i * 64 + r) * 64 + c0];
        #pragma unroll
        for (int j4 = 0; j4 < 8; j4++) {
            float4 v = *(const float4*)&Op[j4 * 4];
            acc[j4 * 4 + 0] += w * v.x;
            acc[j4 * 4 + 1] += w * v.y;
            acc[j4 * 4 + 2] += w * v.z;
            acc[j4 * 4 + 3] += w * v.w;
        }
    }

    const float inv = 1.0f / wl;
    float* o = &out[(qblk * 64 + r) * D_OUT + c0];
    #pragma unroll
    for (int j4 = 0; j4 < 8; j4++) {
        *(float4*)&o[j4 * 4] = make_float4(acc[j4 * 4 + 0] * inv,
                                           acc[j4 * 4 + 1] * inv,
                                           acc[j4 * 4 + 2] * inv,
                                           acc[j4 * 4 + 3] * inv);
    }
}

// ---------------------------------------------------------------------------
extern "C" void kernel_launch(void* const* d_in, const int* in_sizes, int n_in,
                              void* d_out, int out_size)
{
    const float* x  = (const float*)d_in[0];
    const float* Wq = (const float*)d_in[1];
    const float* Wk = (const float*)d_in[2];
    const float* Wv = (const float*)d_in[3];
    float* out = (float*)d_out;

    const int attn_smem = 3 * 64 * SMS * 4;  // 52224 bytes
    cudaFuncSetAttribute(attn_chunk_kernel,
                         cudaFuncAttributeMaxDynamicSharedMemorySize, attn_smem);

    dim3 g1(S_LEN / 64, 3);
    qkv_proj_kernel<<<g1, 256>>>(x, Wq, Wk, Wv);
    dim3 g2(MAX_CHUNKS, S_LEN / 64);
    attn_chunk_kernel<<<g2, 128, attn_smem>>>();
    attn_reduce_kernel<<<S_LEN / 64, 128>>>(out);
}